// round 9
// baseline (speedup 1.0000x reference)
#include <cuda_runtime.h>
#include <cuda_bf16.h>
#include <cstdint>

#define DIM   768
#define NH    12
#define HD    64
#define BATCH 8
#define SEQ   1024
#define M_TOT (BATCH * SEQ)   // 8192
#define QKV_N (3 * DIM)       // 2304

// Scratch (no allocation allowed in kernel_launch)
static __device__ float g_qkv[(size_t)M_TOT * QKV_N];
static __device__ __nv_bfloat16 g_xh[(size_t)M_TOT * DIM];
static __device__ __nv_bfloat16 g_xl[(size_t)M_TOT * DIM];
static __device__ __nv_bfloat16 g_qwh[(size_t)QKV_N * DIM];
static __device__ __nv_bfloat16 g_qwl[(size_t)QKV_N * DIM];
static __device__ __nv_bfloat16 g_pwh[(size_t)DIM * DIM];
static __device__ __nv_bfloat16 g_pwl[(size_t)DIM * DIM];
static __device__ __nv_bfloat16 g_ah[(size_t)M_TOT * DIM];
static __device__ __nv_bfloat16 g_al[(size_t)M_TOT * DIM];

// ---------------------------------------------------------------------------
// helpers
// ---------------------------------------------------------------------------
__device__ __forceinline__ uint32_t smem_u32(const void* p) {
    uint32_t a;
    asm("{ .reg .u64 t; cvta.to.shared.u64 t, %1; cvt.u32.u64 %0, t; }"
        : "=r"(a) : "l"(p));
    return a;
}
__device__ __forceinline__ void split1(float v, __nv_bfloat16& h, __nv_bfloat16& l) {
    h = __float2bfloat16(v);
    l = __float2bfloat16(v - __bfloat162float(h));
}
__device__ __forceinline__ uint32_t pack2(__nv_bfloat16 a, __nv_bfloat16 b) {
    return (uint32_t)__bfloat16_as_ushort(a) |
           ((uint32_t)__bfloat16_as_ushort(b) << 16);
}
__device__ __forceinline__ void split_pair(float a, float b,
                                           uint32_t& hi, uint32_t& lo) {
    __nv_bfloat16 ha, la, hb, lb;
    split1(a, ha, la); split1(b, hb, lb);
    hi = pack2(ha, hb); lo = pack2(la, lb);
}

#define LDX4(r, addr)                                                        \
    asm volatile("ldmatrix.sync.aligned.m8n8.x4.shared.b16 {%0,%1,%2,%3}, [%4];" \
        : "=r"((r)[0]), "=r"((r)[1]), "=r"((r)[2]), "=r"((r)[3])             \
        : "r"(addr))

#define LDX4T(r, addr)                                                       \
    asm volatile("ldmatrix.sync.aligned.m8n8.x4.trans.shared.b16 {%0,%1,%2,%3}, [%4];" \
        : "=r"((r)[0]), "=r"((r)[1]), "=r"((r)[2]), "=r"((r)[3])             \
        : "r"(addr))

#define MMA_BF16(c, a, b0, b1)                                               \
    asm volatile("mma.sync.aligned.m16n8k16.row.col.f32.bf16.bf16.f32 "      \
        "{%0,%1,%2,%3},{%4,%5,%6,%7},{%8,%9},{%0,%1,%2,%3};"                 \
        : "+f"((c)[0]), "+f"((c)[1]), "+f"((c)[2]), "+f"((c)[3])             \
        : "r"((a)[0]), "r"((a)[1]), "r"((a)[2]), "r"((a)[3]),                \
          "r"(b0), "r"(b1))

#define CP16(dst, src)                                                       \
    asm volatile("cp.async.ca.shared.global [%0], [%1], 16;"                 \
        :: "r"((uint32_t)(dst)), "l"(src))
#define CP_COMMIT()  asm volatile("cp.async.commit_group;" ::: "memory")
#define CP_WAIT(n)   asm volatile("cp.async.wait_group %0;" :: "n"(n) : "memory")

// ---------------------------------------------------------------------------
// f32 -> (hi, lo) bf16 split
// ---------------------------------------------------------------------------
__global__ void split_kernel(const float* __restrict__ in,
                             __nv_bfloat16* __restrict__ h,
                             __nv_bfloat16* __restrict__ l, int n)
{
    int i = (blockIdx.x * blockDim.x + threadIdx.x) * 4;
    if (i >= n) return;
    float4 v = *(const float4*)(in + i);
    uint32_t h0, l0, h1, l1;
    split_pair(v.x, v.y, h0, l0);
    split_pair(v.z, v.w, h1, l1);
    *(uint2*)(h + i) = make_uint2(h0, h1);
    *(uint2*)(l + i) = make_uint2(l0, l1);
}

// ---------------------------------------------------------------------------
// bf16 3-term GEMM v3: 128x128 CTA, 128 threads, 4 warps of 64x64.
// cp.async double-buffered smem. 16 LDX4 : 96 MMA per warp per k16.
// ---------------------------------------------------------------------------
#define SB 40
#define ARR_B (128 * SB * 2)          // 10240 bytes per array
#define BUF_B (4 * ARR_B)             // Ah,Al,Bh,Bl = 40960
#define GEMM_SMEM (2 * BUF_B)         // 81920

__global__ __launch_bounds__(128) void gemm_bf16x3(
    const __nv_bfloat16* __restrict__ Ah, const __nv_bfloat16* __restrict__ Al,
    const __nv_bfloat16* __restrict__ Bh, const __nv_bfloat16* __restrict__ Bl,
    const float* __restrict__ bias, float* __restrict__ C, int N, int K)
{
    extern __shared__ __align__(16) char smraw[];
    const uint32_t sbase = smem_u32(smraw);

    const int tid  = threadIdx.x;
    const int wid  = tid >> 5;
    const int lane = tid & 31;
    const int wm   = wid & 1;        // 0,1 -> 64-row halves
    const int wn   = wid >> 1;       // 0,1 -> 64-col halves
    const int bm   = blockIdx.y * 128;
    const int bn   = blockIdx.x * 128;

    const uint32_t offA = (uint32_t)(lane & 15) * (SB * 2) + ((lane & 16) ? 16 : 0);
    const uint32_t offB = (uint32_t)(((lane & 16) >> 1) + (lane & 7)) * (SB * 2)
                        + ((lane & 8) ? 16 : 0);

    // staging: one row (128 rows / 128 threads), 4x 16B pieces per array
    const __nv_bfloat16* gAh = Ah + (size_t)(bm + tid) * K;
    const __nv_bfloat16* gAl = Al + (size_t)(bm + tid) * K;
    const __nv_bfloat16* gBh = Bh + (size_t)(bn + tid) * K;
    const __nv_bfloat16* gBl = Bl + (size_t)(bn + tid) * K;
    const uint32_t drow = (uint32_t)tid * (SB * 2);

    float acc[4][8][4];
#pragma unroll
    for (int t = 0; t < 4; t++)
#pragma unroll
        for (int u = 0; u < 8; u++)
#pragma unroll
            for (int j = 0; j < 4; j++) acc[t][u][j] = 0.f;

    const int nit = K / 32;

    auto issue = [&](int c) {
        const uint32_t ab = sbase + (uint32_t)((c & 1) * BUF_B) + drow;
        const int k0 = c * 32;
#pragma unroll
        for (int p = 0; p < 4; p++) {
            CP16(ab + p * 16,             gAh + k0 + p * 8);
            CP16(ab + ARR_B + p * 16,     gAl + k0 + p * 8);
            CP16(ab + 2 * ARR_B + p * 16, gBh + k0 + p * 8);
            CP16(ab + 3 * ARR_B + p * 16, gBl + k0 + p * 8);
        }
        CP_COMMIT();
    };

    issue(0);

    for (int c = 0; c < nit; c++) {
        if (c + 1 < nit) { issue(c + 1); CP_WAIT(1); }
        else             { CP_WAIT(0); }
        __syncthreads();

        const uint32_t ab  = sbase + (uint32_t)((c & 1) * BUF_B);
        const uint32_t uAh = ab;
        const uint32_t uAl = ab + ARR_B;
        const uint32_t uBh = ab + 2 * ARR_B;
        const uint32_t uBl = ab + 3 * ARR_B;

#pragma unroll
        for (int kk = 0; kk < 2; kk++) {
            uint32_t ah[4][4], al[4][4];
#pragma unroll
            for (int t = 0; t < 4; t++) {
                uint32_t a = (uint32_t)((wm * 64 + t * 16) * (SB * 2)) + kk * 32 + offA;
                LDX4(ah[t], uAh + a);
                LDX4(al[t], uAl + a);
            }
#pragma unroll
            for (int np = 0; np < 4; np++) {
                uint32_t bh[4], bl[4];
                uint32_t a = (uint32_t)((wn * 64 + np * 16) * (SB * 2)) + kk * 32 + offB;
                LDX4(bh, uBh + a);
                LDX4(bl, uBl + a);
#pragma unroll
                for (int t = 0; t < 4; t++) {
                    const int u = np * 2;
                    MMA_BF16(acc[t][u],     ah[t], bh[0], bh[1]);
                    MMA_BF16(acc[t][u],     ah[t], bl[0], bl[1]);
                    MMA_BF16(acc[t][u],     al[t], bh[0], bh[1]);
                    MMA_BF16(acc[t][u + 1], ah[t], bh[2], bh[3]);
                    MMA_BF16(acc[t][u + 1], ah[t], bl[2], bl[3]);
                    MMA_BF16(acc[t][u + 1], al[t], bh[2], bh[3]);
                }
            }
        }
        __syncthreads();
    }

    // Epilogue
    const int er = lane >> 2;
    const int ec = (lane & 3) * 2;
#pragma unroll
    for (int t = 0; t < 4; t++) {
        const int row = bm + wm * 64 + t * 16 + er;
#pragma unroll
        for (int u = 0; u < 8; u++) {
            const int col = bn + wn * 64 + u * 8 + ec;
            const float b0 = bias[col], b1 = bias[col + 1];
            float2 v0 = {acc[t][u][0] + b0, acc[t][u][1] + b1};
            float2 v1 = {acc[t][u][2] + b0, acc[t][u][3] + b1};
            *(float2*)&C[(size_t)row * N + col]       = v0;
            *(float2*)&C[(size_t)(row + 8) * N + col] = v1;
        }
    }
}

// ---------------------------------------------------------------------------
// Tensor-core flash attention (round-8 version, unchanged)
// ---------------------------------------------------------------------------
#define KSTR 72
#define ASZ  (64 * KSTR * 2)
#define BUFSZ (4 * ASZ)
#define ATTN_SMEM (2 * BUFSZ)

__global__ __launch_bounds__(128) void attn_mma(const float* __restrict__ qkv,
                                                __nv_bfloat16* __restrict__ oh,
                                                __nv_bfloat16* __restrict__ ol)
{
    extern __shared__ __align__(16) char smraw[];
    const uint32_t sb = smem_u32(smraw);

    const int tid  = threadIdx.x;
    const int w    = tid >> 5;
    const int lane = tid & 31;
    const int qt   = blockIdx.x * 64;
    const int b    = blockIdx.y / NH;
    const int h    = blockIdx.y % NH;

    const float* base = qkv + (size_t)b * SEQ * QKV_N + h * HD;

    const uint32_t offA = (uint32_t)(lane & 15) * (KSTR * 2) + ((lane & 16) ? 16 : 0);
    const uint32_t offB = (uint32_t)(((lane & 16) >> 1) + (lane & 7)) * (KSTR * 2)
                        + ((lane & 8) ? 16 : 0);

    const int lr = tid >> 1;
    const int lc = (tid & 1) * 32;
    const uint32_t stoff = (uint32_t)lr * (KSTR * 2) + lc * 2;

    {
        const float* qp = base + (size_t)(qt + lr) * QKV_N + lc;
#pragma unroll
        for (int j = 0; j < 8; j++) {
            float4 v = *(const float4*)(qp + j * 4);
            uint32_t h0, l0, h1, l1;
            split_pair(v.x * 0.125f, v.y * 0.125f, h0, l0);
            split_pair(v.z * 0.125f, v.w * 0.125f, h1, l1);
            *(uint2*)(smraw + stoff + j * 8)       = make_uint2(h0, h1);
            *(uint2*)(smraw + ASZ + stoff + j * 8) = make_uint2(l0, l1);
        }
    }
    __syncthreads();

    uint32_t qh[4][4], ql[4][4];
#pragma unroll
    for (int ks = 0; ks < 4; ks++) {
        uint32_t a = (uint32_t)(w * 16) * (KSTR * 2) + ks * 32 + offA;
        LDX4(qh[ks], sb + a);
        LDX4(ql[ks], sb + ASZ + a);
    }
    __syncthreads();

    const float* kbase = base + DIM + (size_t)lr * QKV_N + lc;
    float4 rk[8], rv[8];
#pragma unroll
    for (int j = 0; j < 8; j++) {
        rk[j] = *(const float4*)(kbase + j * 4);
        rv[j] = *(const float4*)(kbase + DIM + j * 4);
    }

    auto stage = [&](int buf) {
        char* p = smraw + buf * BUFSZ + stoff;
#pragma unroll
        for (int j = 0; j < 8; j++) {
            uint32_t h0, lo0, h1, lo1;
            split_pair(rk[j].x, rk[j].y, h0, lo0);
            split_pair(rk[j].z, rk[j].w, h1, lo1);
            *(uint2*)(p + j * 8)           = make_uint2(h0, h1);
            *(uint2*)(p + ASZ + j * 8)     = make_uint2(lo0, lo1);
            split_pair(rv[j].x, rv[j].y, h0, lo0);
            split_pair(rv[j].z, rv[j].w, h1, lo1);
            *(uint2*)(p + 2 * ASZ + j * 8) = make_uint2(h0, h1);
            *(uint2*)(p + 3 * ASZ + j * 8) = make_uint2(lo0, lo1);
        }
    };

    stage(0);
#pragma unroll
    for (int j = 0; j < 8; j++) {
        rk[j] = *(const float4*)(kbase + 64 * QKV_N + j * 4);
        rv[j] = *(const float4*)(kbase + 64 * QKV_N + DIM + j * 4);
    }
    __syncthreads();

    float oacc[8][4];
#pragma unroll
    for (int u = 0; u < 8; u++)
#pragma unroll
        for (int j = 0; j < 4; j++) oacc[u][j] = 0.f;
    float m0 = -1e30f, m1 = -1e30f, l0 = 0.f, l1 = 0.f;

    const int NT = SEQ / 64;
    for (int kt = 0; kt < NT; kt++) {
        const uint32_t bb  = sb + (uint32_t)((kt & 1) * BUFSZ);
        const uint32_t uKh = bb, uKl = bb + ASZ;
        const uint32_t uVh = bb + 2 * ASZ, uVl = bb + 3 * ASZ;

        float sacc[8][4];
#pragma unroll
        for (int u = 0; u < 8; u++)
#pragma unroll
            for (int j = 0; j < 4; j++) sacc[u][j] = 0.f;

#pragma unroll
        for (int ks = 0; ks < 4; ks++) {
#pragma unroll
            for (int np = 0; np < 4; np++) {
                uint32_t kh[4], kl[4];
                uint32_t a = (uint32_t)(np * 16) * (KSTR * 2) + ks * 32 + offB;
                LDX4(kh, uKh + a);
                LDX4(kl, uKl + a);
                const int u = np * 2;
                MMA_BF16(sacc[u],     qh[ks], kh[0], kh[1]);
                MMA_BF16(sacc[u],     qh[ks], kl[0], kl[1]);
                MMA_BF16(sacc[u],     ql[ks], kh[0], kh[1]);
                MMA_BF16(sacc[u + 1], qh[ks], kh[2], kh[3]);
                MMA_BF16(sacc[u + 1], qh[ks], kl[2], kl[3]);
                MMA_BF16(sacc[u + 1], ql[ks], kh[2], kh[3]);
            }
        }

        float mt0 = -1e30f, mt1 = -1e30f;
#pragma unroll
        for (int u = 0; u < 8; u++) {
            mt0 = fmaxf(mt0, fmaxf(sacc[u][0], sacc[u][1]));
            mt1 = fmaxf(mt1, fmaxf(sacc[u][2], sacc[u][3]));
        }
        mt0 = fmaxf(mt0, __shfl_xor_sync(0xffffffffu, mt0, 1));
        mt0 = fmaxf(mt0, __shfl_xor_sync(0xffffffffu, mt0, 2));
        mt1 = fmaxf(mt1, __shfl_xor_sync(0xffffffffu, mt1, 1));
        mt1 = fmaxf(mt1, __shfl_xor_sync(0xffffffffu, mt1, 2));

        const float mn0 = fmaxf(m0, mt0);
        const float mn1 = fmaxf(m1, mt1);
        const float a0 = __expf(m0 - mn0);
        const float a1 = __expf(m1 - mn1);

        float ls0 = 0.f, ls1 = 0.f;
#pragma unroll
        for (int u = 0; u < 8; u++) {
            sacc[u][0] = __expf(sacc[u][0] - mn0);
            sacc[u][1] = __expf(sacc[u][1] - mn0);
            sacc[u][2] = __expf(sacc[u][2] - mn1);
            sacc[u][3] = __expf(sacc[u][3] - mn1);
            ls0 += sacc[u][0] + sacc[u][1];
            ls1 += sacc[u][2] + sacc[u][3];
        }
        ls0 += __shfl_xor_sync(0xffffffffu, ls0, 1);
        ls0 += __shfl_xor_sync(0xffffffffu, ls0, 2);
        ls1 += __shfl_xor_sync(0xffffffffu, ls1, 1);
        ls1 += __shfl_xor_sync(0xffffffffu, ls1, 2);
        l0 = l0 * a0 + ls0;  m0 = mn0;
        l1 = l1 * a1 + ls1;  m1 = mn1;

#pragma unroll
        for (int u = 0; u < 8; u++) {
            oacc[u][0] *= a0; oacc[u][1] *= a0;
            oacc[u][2] *= a1; oacc[u][3] *= a1;
        }

        if (kt + 1 < NT) {
            stage((kt + 1) & 1);
            if (kt + 2 < NT) {
                const float* np = kbase + (size_t)(kt + 2) * 64 * QKV_N;
#pragma unroll
                for (int j = 0; j < 8; j++) {
                    rk[j] = *(const float4*)(np + j * 4);
                    rv[j] = *(const float4*)(np + DIM + j * 4);
                }
            }
        }

        uint32_t pah[4][4], pal[4][4];
#pragma unroll
        for (int t = 0; t < 4; t++) {
            split_pair(sacc[2 * t][0],     sacc[2 * t][1],     pah[t][0], pal[t][0]);
            split_pair(sacc[2 * t][2],     sacc[2 * t][3],     pah[t][1], pal[t][1]);
            split_pair(sacc[2 * t + 1][0], sacc[2 * t + 1][1], pah[t][2], pal[t][2]);
            split_pair(sacc[2 * t + 1][2], sacc[2 * t + 1][3], pah[t][3], pal[t][3]);
        }

#pragma unroll
        for (int t = 0; t < 4; t++) {
#pragma unroll
            for (int nd = 0; nd < 4; nd++) {
                uint32_t vh[4], vl[4];
                uint32_t a = (uint32_t)(t * 16) * (KSTR * 2) + nd * 32 + offB;
                LDX4T(vh, uVh + a);
                LDX4T(vl, uVl + a);
                const int u = nd * 2;
                MMA_BF16(oacc[u],     pah[t], vh[0], vh[2]);
                MMA_BF16(oacc[u],     pah[t], vl[0], vl[2]);
                MMA_BF16(oacc[u],     pal[t], vh[0], vh[2]);
                MMA_BF16(oacc[u + 1], pah[t], vh[1], vh[3]);
                MMA_BF16(oacc[u + 1], pah[t], vl[1], vl[3]);
                MMA_BF16(oacc[u + 1], pal[t], vh[1], vh[3]);
            }
        }
        __syncthreads();
    }

    const float inv0 = 1.f / l0;
    const float inv1 = 1.f / l1;
    const int er = lane >> 2;
    const int ec = (lane & 3) * 2;
    const size_t tok0 = (size_t)b * SEQ + qt + w * 16 + er;
    const int colb = h * HD + ec;
#pragma unroll
    for (int u = 0; u < 8; u++) {
        const int col = colb + u * 8;
        uint32_t hp, lp;
        split_pair(oacc[u][0] * inv0, oacc[u][1] * inv0, hp, lp);
        *(uint32_t*)(oh + tok0 * DIM + col) = hp;
        *(uint32_t*)(ol + tok0 * DIM + col) = lp;
        split_pair(oacc[u][2] * inv1, oacc[u][3] * inv1, hp, lp);
        *(uint32_t*)(oh + (tok0 + 8) * DIM + col) = hp;
        *(uint32_t*)(ol + (tok0 + 8) * DIM + col) = lp;
    }
}

extern "C" void kernel_launch(void* const* d_in, const int* in_sizes, int n_in,
                              void* d_out, int out_size)
{
    const float* x      = (const float*)d_in[0];
    const float* qkv_w  = (const float*)d_in[1];
    const float* qkv_b  = (const float*)d_in[2];
    const float* proj_w = (const float*)d_in[3];
    const float* proj_b = (const float*)d_in[4];
    float* out = (float*)d_out;

    float* qkv;
    __nv_bfloat16 *xh, *xl, *qwh, *qwl, *pwh, *pwl, *ah, *al;
    cudaGetSymbolAddress((void**)&qkv, g_qkv);
    cudaGetSymbolAddress((void**)&xh,  g_xh);
    cudaGetSymbolAddress((void**)&xl,  g_xl);
    cudaGetSymbolAddress((void**)&qwh, g_qwh);
    cudaGetSymbolAddress((void**)&qwl, g_qwl);
    cudaGetSymbolAddress((void**)&pwh, g_pwh);
    cudaGetSymbolAddress((void**)&pwl, g_pwl);
    cudaGetSymbolAddress((void**)&ah,  g_ah);
    cudaGetSymbolAddress((void**)&al,  g_al);

    cudaFuncSetAttribute(gemm_bf16x3,
                         cudaFuncAttributeMaxDynamicSharedMemorySize, GEMM_SMEM);
    cudaFuncSetAttribute(attn_mma,
                         cudaFuncAttributeMaxDynamicSharedMemorySize, ATTN_SMEM);

    // splits
    const int nx = M_TOT * DIM, nqw = QKV_N * DIM, npw = DIM * DIM;
    split_kernel<<<(nx / 4 + 255) / 256, 256>>>(x, xh, xl, nx);
    split_kernel<<<(nqw / 4 + 255) / 256, 256>>>(qkv_w, qwh, qwl, nqw);
    split_kernel<<<(npw / 4 + 255) / 256, 256>>>(proj_w, pwh, pwl, npw);

    // QKV projection: [8192, 2304]
    gemm_bf16x3<<<dim3(QKV_N / 128, M_TOT / 128), 128, GEMM_SMEM>>>(
        xh, xl, qwh, qwl, qkv_b, qkv, QKV_N, DIM);

    // Attention (tensor-core, pipelined) -> bf16 hi/lo
    attn_mma<<<dim3(SEQ / 64, BATCH * NH), 128, ATTN_SMEM>>>(qkv, ah, al);

    // Output projection: [8192, 768]
    gemm_bf16x3<<<dim3(DIM / 128, M_TOT / 128), 128, GEMM_SMEM>>>(
        ah, al, pwh, pwl, proj_b, out, DIM, DIM);
}

// round 10
// speedup vs baseline: 1.1354x; 1.1354x over previous
#include <cuda_runtime.h>
#include <cuda_bf16.h>
#include <cstdint>

#define DIM   768
#define NH    12
#define HD    64
#define BATCH 8
#define SEQ   1024
#define M_TOT (BATCH * SEQ)   // 8192
#define QKV_N (3 * DIM)       // 2304

// Scratch (no allocation allowed in kernel_launch)
static __device__ __nv_bfloat16 g_qh[(size_t)M_TOT * QKV_N];   // qkv result hi
static __device__ __nv_bfloat16 g_ql[(size_t)M_TOT * QKV_N];   // qkv result lo
static __device__ __nv_bfloat16 g_xh[(size_t)M_TOT * DIM];
static __device__ __nv_bfloat16 g_xl[(size_t)M_TOT * DIM];
static __device__ __nv_bfloat16 g_qwh[(size_t)QKV_N * DIM];
static __device__ __nv_bfloat16 g_qwl[(size_t)QKV_N * DIM];
static __device__ __nv_bfloat16 g_pwh[(size_t)DIM * DIM];
static __device__ __nv_bfloat16 g_pwl[(size_t)DIM * DIM];
static __device__ __nv_bfloat16 g_ah[(size_t)M_TOT * DIM];
static __device__ __nv_bfloat16 g_al[(size_t)M_TOT * DIM];

// ---------------------------------------------------------------------------
// helpers
// ---------------------------------------------------------------------------
__device__ __forceinline__ uint32_t smem_u32(const void* p) {
    uint32_t a;
    asm("{ .reg .u64 t; cvta.to.shared.u64 t, %1; cvt.u32.u64 %0, t; }"
        : "=r"(a) : "l"(p));
    return a;
}
__device__ __forceinline__ void split1(float v, __nv_bfloat16& h, __nv_bfloat16& l) {
    h = __float2bfloat16(v);
    l = __float2bfloat16(v - __bfloat162float(h));
}
__device__ __forceinline__ uint32_t pack2(__nv_bfloat16 a, __nv_bfloat16 b) {
    return (uint32_t)__bfloat16_as_ushort(a) |
           ((uint32_t)__bfloat16_as_ushort(b) << 16);
}
__device__ __forceinline__ void split_pair(float a, float b,
                                           uint32_t& hi, uint32_t& lo) {
    __nv_bfloat16 ha, la, hb, lb;
    split1(a, ha, la); split1(b, hb, lb);
    hi = pack2(ha, hb); lo = pack2(la, lb);
}

#define LDX4(r, addr)                                                        \
    asm volatile("ldmatrix.sync.aligned.m8n8.x4.shared.b16 {%0,%1,%2,%3}, [%4];" \
        : "=r"((r)[0]), "=r"((r)[1]), "=r"((r)[2]), "=r"((r)[3])             \
        : "r"(addr))

#define LDX4T(r, addr)                                                       \
    asm volatile("ldmatrix.sync.aligned.m8n8.x4.trans.shared.b16 {%0,%1,%2,%3}, [%4];" \
        : "=r"((r)[0]), "=r"((r)[1]), "=r"((r)[2]), "=r"((r)[3])             \
        : "r"(addr))

#define MMA_BF16(c, a, b0, b1)                                               \
    asm volatile("mma.sync.aligned.m16n8k16.row.col.f32.bf16.bf16.f32 "      \
        "{%0,%1,%2,%3},{%4,%5,%6,%7},{%8,%9},{%0,%1,%2,%3};"                 \
        : "+f"((c)[0]), "+f"((c)[1]), "+f"((c)[2]), "+f"((c)[3])             \
        : "r"((a)[0]), "r"((a)[1]), "r"((a)[2]), "r"((a)[3]),                \
          "r"(b0), "r"(b1))

#define CP16(dst, src)                                                       \
    asm volatile("cp.async.ca.shared.global [%0], [%1], 16;"                 \
        :: "r"((uint32_t)(dst)), "l"(src))
#define CP_COMMIT()  asm volatile("cp.async.commit_group;" ::: "memory")
#define CP_WAIT(n)   asm volatile("cp.async.wait_group %0;" :: "n"(n) : "memory")

// ---------------------------------------------------------------------------
// f32 -> (hi, lo) bf16 split
// ---------------------------------------------------------------------------
__global__ void split_kernel(const float* __restrict__ in,
                             __nv_bfloat16* __restrict__ h,
                             __nv_bfloat16* __restrict__ l, int n)
{
    int i = (blockIdx.x * blockDim.x + threadIdx.x) * 4;
    if (i >= n) return;
    float4 v = *(const float4*)(in + i);
    uint32_t h0, l0, h1, l1;
    split_pair(v.x, v.y, h0, l0);
    split_pair(v.z, v.w, h1, l1);
    *(uint2*)(h + i) = make_uint2(h0, h1);
    *(uint2*)(l + i) = make_uint2(l0, l1);
}

// ---------------------------------------------------------------------------
// bf16 3-term GEMM (round-8 core: 128x128 CTA, 256 thr, 8 warps of 64x32).
// SPLIT=false: C = f32 out.  SPLIT=true: write bf16 hi/lo (Ch, Cl).
// ---------------------------------------------------------------------------
#define SB 40

template <bool SPLIT>
__global__ __launch_bounds__(256) void gemm_bf16x3(
    const __nv_bfloat16* __restrict__ Ah, const __nv_bfloat16* __restrict__ Al,
    const __nv_bfloat16* __restrict__ Bh, const __nv_bfloat16* __restrict__ Bl,
    const float* __restrict__ bias, float* __restrict__ C,
    __nv_bfloat16* __restrict__ Ch, __nv_bfloat16* __restrict__ Cl,
    int N, int K)
{
    __shared__ __align__(16) __nv_bfloat16 sAh[128 * SB];
    __shared__ __align__(16) __nv_bfloat16 sAl[128 * SB];
    __shared__ __align__(16) __nv_bfloat16 sBh[128 * SB];
    __shared__ __align__(16) __nv_bfloat16 sBl[128 * SB];

    const int tid  = threadIdx.x;
    const int wid  = tid >> 5;
    const int lane = tid & 31;
    const int wm   = wid & 1;
    const int wn   = wid >> 1;
    const int bm   = blockIdx.y * 128;
    const int bn   = blockIdx.x * 128;

    const uint32_t uAh = smem_u32(sAh), uAl = smem_u32(sAl);
    const uint32_t uBh = smem_u32(sBh), uBl = smem_u32(sBl);

    const uint32_t offA = (uint32_t)(lane & 15) * (SB * 2) + ((lane & 16) ? 16 : 0);
    const uint32_t offB = (uint32_t)(((lane & 16) >> 1) + (lane & 7)) * (SB * 2)
                        + ((lane & 8) ? 16 : 0);

    const int lrow = tid >> 1;
    const int cb   = (tid & 1) * 16;
    const __nv_bfloat16* pAh = Ah + (size_t)(bm + lrow) * K + cb;
    const __nv_bfloat16* pAl = Al + (size_t)(bm + lrow) * K + cb;
    const __nv_bfloat16* pBh = Bh + (size_t)(bn + lrow) * K + cb;
    const __nv_bfloat16* pBl = Bl + (size_t)(bn + lrow) * K + cb;
    __nv_bfloat16* qAh = &sAh[lrow * SB + cb];
    __nv_bfloat16* qAl = &sAl[lrow * SB + cb];
    __nv_bfloat16* qBh = &sBh[lrow * SB + cb];
    __nv_bfloat16* qBl = &sBl[lrow * SB + cb];

    float acc[4][4][4];
#pragma unroll
    for (int t = 0; t < 4; t++)
#pragma unroll
        for (int u = 0; u < 4; u++)
#pragma unroll
            for (int j = 0; j < 4; j++) acc[t][u][j] = 0.f;

    const int nit = K / 32;
    uint4 rah0 = *(const uint4*)(pAh);     uint4 rah1 = *(const uint4*)(pAh + 8);
    uint4 ral0 = *(const uint4*)(pAl);     uint4 ral1 = *(const uint4*)(pAl + 8);
    uint4 rbh0 = *(const uint4*)(pBh);     uint4 rbh1 = *(const uint4*)(pBh + 8);
    uint4 rbl0 = *(const uint4*)(pBl);     uint4 rbl1 = *(const uint4*)(pBl + 8);

    for (int c = 0; c < nit; c++) {
        *(uint4*)(qAh) = rah0; *(uint4*)(qAh + 8) = rah1;
        *(uint4*)(qAl) = ral0; *(uint4*)(qAl + 8) = ral1;
        *(uint4*)(qBh) = rbh0; *(uint4*)(qBh + 8) = rbh1;
        *(uint4*)(qBl) = rbl0; *(uint4*)(qBl + 8) = rbl1;
        __syncthreads();

        if (c + 1 < nit) {
            const int k0 = (c + 1) * 32;
            rah0 = *(const uint4*)(pAh + k0); rah1 = *(const uint4*)(pAh + k0 + 8);
            ral0 = *(const uint4*)(pAl + k0); ral1 = *(const uint4*)(pAl + k0 + 8);
            rbh0 = *(const uint4*)(pBh + k0); rbh1 = *(const uint4*)(pBh + k0 + 8);
            rbl0 = *(const uint4*)(pBl + k0); rbl1 = *(const uint4*)(pBl + k0 + 8);
        }

#pragma unroll
        for (int kk = 0; kk < 32; kk += 16) {
            uint32_t ah[4][4], al[4][4], bh[2][4], bl[2][4];
#pragma unroll
            for (int t = 0; t < 4; t++) {
                uint32_t base = (uint32_t)((wm * 64 + t * 16) * (SB * 2)) + kk * 2;
                LDX4(ah[t], uAh + base + offA);
                LDX4(al[t], uAl + base + offA);
            }
#pragma unroll
            for (int p = 0; p < 2; p++) {
                uint32_t base = (uint32_t)((wn * 32 + p * 16) * (SB * 2)) + kk * 2;
                LDX4(bh[p], uBh + base + offB);
                LDX4(bl[p], uBl + base + offB);
            }
#pragma unroll
            for (int t = 0; t < 4; t++) {
#pragma unroll
                for (int u = 0; u < 4; u++) {
                    const int p = u >> 1, o = (u & 1) * 2;
                    MMA_BF16(acc[t][u], ah[t], bh[p][o], bh[p][o + 1]);
                    MMA_BF16(acc[t][u], ah[t], bl[p][o], bl[p][o + 1]);
                    MMA_BF16(acc[t][u], al[t], bh[p][o], bh[p][o + 1]);
                }
            }
        }
        __syncthreads();
    }

    const int er = lane >> 2;
    const int ec = (lane & 3) * 2;
#pragma unroll
    for (int t = 0; t < 4; t++) {
        const int row = bm + wm * 64 + t * 16 + er;
#pragma unroll
        for (int u = 0; u < 4; u++) {
            const int col = bn + wn * 32 + u * 8 + ec;
            const float b0 = bias[col], b1 = bias[col + 1];
            if (!SPLIT) {
                float2 v0 = {acc[t][u][0] + b0, acc[t][u][1] + b1};
                float2 v1 = {acc[t][u][2] + b0, acc[t][u][3] + b1};
                *(float2*)&C[(size_t)row * N + col]       = v0;
                *(float2*)&C[(size_t)(row + 8) * N + col] = v1;
            } else {
                uint32_t hp, lp;
                split_pair(acc[t][u][0] + b0, acc[t][u][1] + b1, hp, lp);
                *(uint32_t*)&Ch[(size_t)row * N + col] = hp;
                *(uint32_t*)&Cl[(size_t)row * N + col] = lp;
                split_pair(acc[t][u][2] + b0, acc[t][u][3] + b1, hp, lp);
                *(uint32_t*)&Ch[(size_t)(row + 8) * N + col] = hp;
                *(uint32_t*)&Cl[(size_t)(row + 8) * N + col] = lp;
            }
        }
    }
}

// ---------------------------------------------------------------------------
// Tensor-core flash attention v4: Q/K/V arrive pre-split (bf16 hi/lo).
// cp.async double-buffered K/V staging. 128 thr, 64 q-rows/CTA.
// ---------------------------------------------------------------------------
#define KSTR 72
#define ASZ  (64 * KSTR * 2)      // 9216 bytes per array
#define BUFSZ (4 * ASZ)           // Kh,Kl,Vh,Vl = 36864
#define ATTN_SMEM (2 * BUFSZ)     // 73728

__global__ __launch_bounds__(128) void attn_mma(
    const __nv_bfloat16* __restrict__ qh_g,
    const __nv_bfloat16* __restrict__ ql_g,
    __nv_bfloat16* __restrict__ oh, __nv_bfloat16* __restrict__ ol)
{
    extern __shared__ __align__(16) char smraw[];
    const uint32_t sb = smem_u32(smraw);

    const int tid  = threadIdx.x;
    const int w    = tid >> 5;
    const int lane = tid & 31;
    const int qt   = blockIdx.x * 64;
    const int b    = blockIdx.y / NH;
    const int h    = blockIdx.y % NH;

    const uint32_t offA = (uint32_t)(lane & 15) * (KSTR * 2) + ((lane & 16) ? 16 : 0);
    const uint32_t offB = (uint32_t)(((lane & 16) >> 1) + (lane & 7)) * (KSTR * 2)
                        + ((lane & 8) ? 16 : 0);

    // staging mapping: row = tid/2 (0..63), half = (tid&1) -> 64B (4x16B)
    const int lr   = tid >> 1;
    const int half = tid & 1;
    const uint32_t dst0 = (uint32_t)lr * (KSTR * 2) + half * 64;   // byte offset
    // element offset within a row of the bf16 source (64 elems per head)
    const int selem = half * 32;

    // ---- stage Q (pre-split) into buf0 Kh/Kl via cp.async; pull A-frags ----
    {
        const size_t qoff = ((size_t)(b * SEQ + qt + lr)) * QKV_N + h * HD + selem;
#pragma unroll
        for (int p = 0; p < 4; p++) {
            CP16(sb + dst0 + p * 16,       qh_g + qoff + p * 8);
            CP16(sb + ASZ + dst0 + p * 16, ql_g + qoff + p * 8);
        }
        CP_COMMIT();
        CP_WAIT(0);
    }
    __syncthreads();

    uint32_t qh[4][4], ql[4][4];
#pragma unroll
    for (int ks = 0; ks < 4; ks++) {
        uint32_t a = (uint32_t)(w * 16) * (KSTR * 2) + ks * 32 + offA;
        LDX4(qh[ks], sb + a);
        LDX4(ql[ks], sb + ASZ + a);
    }
    __syncthreads();

    const int NT = SEQ / 64;

    // issue K/V tile kt into buffer (kt & 1)
    const size_t kvbase = ((size_t)(b * SEQ + lr)) * QKV_N + DIM + h * HD + selem;
    auto issue = [&](int kt) {
        const uint32_t db = sb + (uint32_t)((kt & 1) * BUFSZ) + dst0;
        const size_t so = kvbase + (size_t)kt * 64 * QKV_N;
#pragma unroll
        for (int p = 0; p < 4; p++) {
            CP16(db + p * 16,           qh_g + so + p * 8);          // Kh
            CP16(db + ASZ + p * 16,     ql_g + so + p * 8);          // Kl
            CP16(db + 2 * ASZ + p * 16, qh_g + so + DIM + p * 8);    // Vh
            CP16(db + 3 * ASZ + p * 16, ql_g + so + DIM + p * 8);    // Vl
        }
        CP_COMMIT();
    };

    issue(0);
    issue(1);

    float oacc[8][4];
#pragma unroll
    for (int u = 0; u < 8; u++)
#pragma unroll
        for (int j = 0; j < 4; j++) oacc[u][j] = 0.f;
    float m0 = -1e30f, m1 = -1e30f, l0 = 0.f, l1 = 0.f;

    for (int kt = 0; kt < NT; kt++) {
        if (kt == NT - 1) { CP_WAIT(0); } else { CP_WAIT(1); }
        __syncthreads();

        const uint32_t bb  = sb + (uint32_t)((kt & 1) * BUFSZ);
        const uint32_t uKh = bb, uKl = bb + ASZ;
        const uint32_t uVh = bb + 2 * ASZ, uVl = bb + 3 * ASZ;

        // ---- S = Q @ K^T (3-term) ----
        float sacc[8][4];
#pragma unroll
        for (int u = 0; u < 8; u++)
#pragma unroll
            for (int j = 0; j < 4; j++) sacc[u][j] = 0.f;

#pragma unroll
        for (int ks = 0; ks < 4; ks++) {
#pragma unroll
            for (int np = 0; np < 4; np++) {
                uint32_t kh[4], kl[4];
                uint32_t a = (uint32_t)(np * 16) * (KSTR * 2) + ks * 32 + offB;
                LDX4(kh, uKh + a);
                LDX4(kl, uKl + a);
                const int u = np * 2;
                MMA_BF16(sacc[u],     qh[ks], kh[0], kh[1]);
                MMA_BF16(sacc[u],     qh[ks], kl[0], kl[1]);
                MMA_BF16(sacc[u],     ql[ks], kh[0], kh[1]);
                MMA_BF16(sacc[u + 1], qh[ks], kh[2], kh[3]);
                MMA_BF16(sacc[u + 1], qh[ks], kl[2], kl[3]);
                MMA_BF16(sacc[u + 1], ql[ks], kh[2], kh[3]);
            }
        }

        // ---- scale + online softmax ----
#pragma unroll
        for (int u = 0; u < 8; u++) {
            sacc[u][0] *= 0.125f; sacc[u][1] *= 0.125f;
            sacc[u][2] *= 0.125f; sacc[u][3] *= 0.125f;
        }
        float mt0 = -1e30f, mt1 = -1e30f;
#pragma unroll
        for (int u = 0; u < 8; u++) {
            mt0 = fmaxf(mt0, fmaxf(sacc[u][0], sacc[u][1]));
            mt1 = fmaxf(mt1, fmaxf(sacc[u][2], sacc[u][3]));
        }
        mt0 = fmaxf(mt0, __shfl_xor_sync(0xffffffffu, mt0, 1));
        mt0 = fmaxf(mt0, __shfl_xor_sync(0xffffffffu, mt0, 2));
        mt1 = fmaxf(mt1, __shfl_xor_sync(0xffffffffu, mt1, 1));
        mt1 = fmaxf(mt1, __shfl_xor_sync(0xffffffffu, mt1, 2));

        const float mn0 = fmaxf(m0, mt0);
        const float mn1 = fmaxf(m1, mt1);
        const float a0 = __expf(m0 - mn0);
        const float a1 = __expf(m1 - mn1);

        float ls0 = 0.f, ls1 = 0.f;
#pragma unroll
        for (int u = 0; u < 8; u++) {
            sacc[u][0] = __expf(sacc[u][0] - mn0);
            sacc[u][1] = __expf(sacc[u][1] - mn0);
            sacc[u][2] = __expf(sacc[u][2] - mn1);
            sacc[u][3] = __expf(sacc[u][3] - mn1);
            ls0 += sacc[u][0] + sacc[u][1];
            ls1 += sacc[u][2] + sacc[u][3];
        }
        ls0 += __shfl_xor_sync(0xffffffffu, ls0, 1);
        ls0 += __shfl_xor_sync(0xffffffffu, ls0, 2);
        ls1 += __shfl_xor_sync(0xffffffffu, ls1, 1);
        ls1 += __shfl_xor_sync(0xffffffffu, ls1, 2);
        l0 = l0 * a0 + ls0;  m0 = mn0;
        l1 = l1 * a1 + ls1;  m1 = mn1;

#pragma unroll
        for (int u = 0; u < 8; u++) {
            oacc[u][0] *= a0; oacc[u][1] *= a0;
            oacc[u][2] *= a1; oacc[u][3] *= a1;
        }

        // ---- pack P into A-frags (hi/lo) ----
        uint32_t pah[4][4], pal[4][4];
#pragma unroll
        for (int t = 0; t < 4; t++) {
            split_pair(sacc[2 * t][0],     sacc[2 * t][1],     pah[t][0], pal[t][0]);
            split_pair(sacc[2 * t][2],     sacc[2 * t][3],     pah[t][1], pal[t][1]);
            split_pair(sacc[2 * t + 1][0], sacc[2 * t + 1][1], pah[t][2], pal[t][2]);
            split_pair(sacc[2 * t + 1][2], sacc[2 * t + 1][3], pah[t][3], pal[t][3]);
        }

        // ---- O += P @ V (3-term; V via ldmatrix.trans) ----
#pragma unroll
        for (int t = 0; t < 4; t++) {
#pragma unroll
            for (int nd = 0; nd < 4; nd++) {
                uint32_t vh[4], vl[4];
                uint32_t a = (uint32_t)(t * 16) * (KSTR * 2) + nd * 32 + offB;
                LDX4T(vh, uVh + a);
                LDX4T(vl, uVl + a);
                const int u = nd * 2;
                MMA_BF16(oacc[u],     pah[t], vh[0], vh[2]);
                MMA_BF16(oacc[u],     pah[t], vl[0], vl[2]);
                MMA_BF16(oacc[u],     pal[t], vh[0], vh[2]);
                MMA_BF16(oacc[u + 1], pah[t], vh[1], vh[3]);
                MMA_BF16(oacc[u + 1], pah[t], vl[1], vl[3]);
                MMA_BF16(oacc[u + 1], pal[t], vh[1], vh[3]);
            }
        }
        __syncthreads();

        if (kt + 2 < NT) issue(kt + 2);
    }

    // ---- epilogue ----
    const float inv0 = 1.f / l0;
    const float inv1 = 1.f / l1;
    const int er = lane >> 2;
    const int ec = (lane & 3) * 2;
    const size_t tok0 = (size_t)b * SEQ + qt + w * 16 + er;
    const int colb = h * HD + ec;
#pragma unroll
    for (int u = 0; u < 8; u++) {
        const int col = colb + u * 8;
        uint32_t hp, lp;
        split_pair(oacc[u][0] * inv0, oacc[u][1] * inv0, hp, lp);
        *(uint32_t*)(oh + tok0 * DIM + col) = hp;
        *(uint32_t*)(ol + tok0 * DIM + col) = lp;
        split_pair(oacc[u][2] * inv1, oacc[u][3] * inv1, hp, lp);
        *(uint32_t*)(oh + (tok0 + 8) * DIM + col) = hp;
        *(uint32_t*)(ol + (tok0 + 8) * DIM + col) = lp;
    }
}

extern "C" void kernel_launch(void* const* d_in, const int* in_sizes, int n_in,
                              void* d_out, int out_size)
{
    const float* x      = (const float*)d_in[0];
    const float* qkv_w  = (const float*)d_in[1];
    const float* qkv_b  = (const float*)d_in[2];
    const float* proj_w = (const float*)d_in[3];
    const float* proj_b = (const float*)d_in[4];
    float* out = (float*)d_out;

    __nv_bfloat16 *qh, *ql, *xh, *xl, *qwh, *qwl, *pwh, *pwl, *ah, *al;
    cudaGetSymbolAddress((void**)&qh,  g_qh);
    cudaGetSymbolAddress((void**)&ql,  g_ql);
    cudaGetSymbolAddress((void**)&xh,  g_xh);
    cudaGetSymbolAddress((void**)&xl,  g_xl);
    cudaGetSymbolAddress((void**)&qwh, g_qwh);
    cudaGetSymbolAddress((void**)&qwl, g_qwl);
    cudaGetSymbolAddress((void**)&pwh, g_pwh);
    cudaGetSymbolAddress((void**)&pwl, g_pwl);
    cudaGetSymbolAddress((void**)&ah,  g_ah);
    cudaGetSymbolAddress((void**)&al,  g_al);

    cudaFuncSetAttribute(attn_mma,
                         cudaFuncAttributeMaxDynamicSharedMemorySize, ATTN_SMEM);

    // splits of kernel inputs
    const int nx = M_TOT * DIM, nqw = QKV_N * DIM, npw = DIM * DIM;
    split_kernel<<<(nx / 4 + 255) / 256, 256>>>(x, xh, xl, nx);
    split_kernel<<<(nqw / 4 + 255) / 256, 256>>>(qkv_w, qwh, qwl, nqw);
    split_kernel<<<(npw / 4 + 255) / 256, 256>>>(proj_w, pwh, pwl, npw);

    // QKV projection -> bf16 hi/lo directly
    gemm_bf16x3<true><<<dim3(QKV_N / 128, M_TOT / 128), 256>>>(
        xh, xl, qwh, qwl, qkv_b, nullptr, qh, ql, QKV_N, DIM);

    // Attention (tensor-core, cp.async pipelined) -> bf16 hi/lo
    attn_mma<<<dim3(SEQ / 64, BATCH * NH), 128, ATTN_SMEM>>>(qh, ql, ah, al);

    // Output projection -> f32
    gemm_bf16x3<false><<<dim3(DIM / 128, M_TOT / 128), 256>>>(
        ah, al, pwh, pwl, proj_b, out, nullptr, nullptr, DIM, DIM);
}

// round 11
// speedup vs baseline: 1.2156x; 1.0706x over previous
#include <cuda_runtime.h>
#include <cuda_bf16.h>
#include <cstdint>

#define DIM   768
#define NH    12
#define HD    64
#define BATCH 8
#define SEQ   1024
#define M_TOT (BATCH * SEQ)   // 8192
#define QKV_N (3 * DIM)       // 2304

// Scratch (no allocation allowed in kernel_launch)
static __device__ float g_qkv[(size_t)M_TOT * QKV_N];
static __device__ __nv_bfloat16 g_xh[(size_t)M_TOT * DIM];
static __device__ __nv_bfloat16 g_xl[(size_t)M_TOT * DIM];
static __device__ __nv_bfloat16 g_qwh[(size_t)QKV_N * DIM];
static __device__ __nv_bfloat16 g_qwl[(size_t)QKV_N * DIM];
static __device__ __nv_bfloat16 g_pwh[(size_t)DIM * DIM];
static __device__ __nv_bfloat16 g_pwl[(size_t)DIM * DIM];
static __device__ __nv_bfloat16 g_ah[(size_t)M_TOT * DIM];
static __device__ __nv_bfloat16 g_al[(size_t)M_TOT * DIM];

// ---------------------------------------------------------------------------
// helpers
// ---------------------------------------------------------------------------
__device__ __forceinline__ uint32_t smem_u32(const void* p) {
    uint32_t a;
    asm("{ .reg .u64 t; cvta.to.shared.u64 t, %1; cvt.u32.u64 %0, t; }"
        : "=r"(a) : "l"(p));
    return a;
}
__device__ __forceinline__ void split1(float v, __nv_bfloat16& h, __nv_bfloat16& l) {
    h = __float2bfloat16(v);
    l = __float2bfloat16(v - __bfloat162float(h));
}
__device__ __forceinline__ uint32_t pack2(__nv_bfloat16 a, __nv_bfloat16 b) {
    return (uint32_t)__bfloat16_as_ushort(a) |
           ((uint32_t)__bfloat16_as_ushort(b) << 16);
}
__device__ __forceinline__ void split_pair(float a, float b,
                                           uint32_t& hi, uint32_t& lo) {
    __nv_bfloat16 ha, la, hb, lb;
    split1(a, ha, la); split1(b, hb, lb);
    hi = pack2(ha, hb); lo = pack2(la, lb);
}

#define LDX4(r, addr)                                                        \
    asm volatile("ldmatrix.sync.aligned.m8n8.x4.shared.b16 {%0,%1,%2,%3}, [%4];" \
        : "=r"((r)[0]), "=r"((r)[1]), "=r"((r)[2]), "=r"((r)[3])             \
        : "r"(addr))

#define LDX4T(r, addr)                                                       \
    asm volatile("ldmatrix.sync.aligned.m8n8.x4.trans.shared.b16 {%0,%1,%2,%3}, [%4];" \
        : "=r"((r)[0]), "=r"((r)[1]), "=r"((r)[2]), "=r"((r)[3])             \
        : "r"(addr))

#define MMA_BF16(c, a, b0, b1)                                               \
    asm volatile("mma.sync.aligned.m16n8k16.row.col.f32.bf16.bf16.f32 "      \
        "{%0,%1,%2,%3},{%4,%5,%6,%7},{%8,%9},{%0,%1,%2,%3};"                 \
        : "+f"((c)[0]), "+f"((c)[1]), "+f"((c)[2]), "+f"((c)[3])             \
        : "r"((a)[0]), "r"((a)[1]), "r"((a)[2]), "r"((a)[3]),                \
          "r"(b0), "r"(b1))

#define CP16(dst, src)                                                       \
    asm volatile("cp.async.ca.shared.global [%0], [%1], 16;"                 \
        :: "r"((uint32_t)(dst)), "l"(src))
#define CP_COMMIT()  asm volatile("cp.async.commit_group;" ::: "memory")
#define CP_WAIT(n)   asm volatile("cp.async.wait_group %0;" :: "n"(n) : "memory")

// ---------------------------------------------------------------------------
// f32 -> (hi, lo) bf16 split
// ---------------------------------------------------------------------------
__global__ void split_kernel(const float* __restrict__ in,
                             __nv_bfloat16* __restrict__ h,
                             __nv_bfloat16* __restrict__ l, int n)
{
    int i = (blockIdx.x * blockDim.x + threadIdx.x) * 4;
    if (i >= n) return;
    float4 v = *(const float4*)(in + i);
    uint32_t h0, l0, h1, l1;
    split_pair(v.x, v.y, h0, l0);
    split_pair(v.z, v.w, h1, l1);
    *(uint2*)(h + i) = make_uint2(h0, h1);
    *(uint2*)(l + i) = make_uint2(l0, l1);
}

// ---------------------------------------------------------------------------
// bf16 3-term GEMM v4: round-8 tile shape (128x128 CTA, 256 thr, 8 warps of
// 64x32) but cp.async double-buffered staging (frees 64 prefetch regs ->
// 2 CTAs/SM).
// ---------------------------------------------------------------------------
#define SB 40
#define ARR_B (128 * SB * 2)          // 10240 bytes per array
#define BUF_B (4 * ARR_B)             // Ah,Al,Bh,Bl = 40960
#define GEMM_SMEM (2 * BUF_B)         // 81920

__global__ __launch_bounds__(256, 2) void gemm_bf16x3(
    const __nv_bfloat16* __restrict__ Ah, const __nv_bfloat16* __restrict__ Al,
    const __nv_bfloat16* __restrict__ Bh, const __nv_bfloat16* __restrict__ Bl,
    const float* __restrict__ bias, float* __restrict__ C, int N, int K)
{
    extern __shared__ __align__(16) char smraw[];
    const uint32_t sbase = smem_u32(smraw);

    const int tid  = threadIdx.x;
    const int wid  = tid >> 5;
    const int lane = tid & 31;
    const int wm   = wid & 1;
    const int wn   = wid >> 1;
    const int bm   = blockIdx.y * 128;
    const int bn   = blockIdx.x * 128;

    const uint32_t offA = (uint32_t)(lane & 15) * (SB * 2) + ((lane & 16) ? 16 : 0);
    const uint32_t offB = (uint32_t)(((lane & 16) >> 1) + (lane & 7)) * (SB * 2)
                        + ((lane & 8) ? 16 : 0);

    // staging: row = tid/2 (0..127), col half = (tid&1)*16 elems (32 B)
    const int lrow = tid >> 1;
    const int cb   = (tid & 1) * 16;
    const __nv_bfloat16* pAh = Ah + (size_t)(bm + lrow) * K + cb;
    const __nv_bfloat16* pAl = Al + (size_t)(bm + lrow) * K + cb;
    const __nv_bfloat16* pBh = Bh + (size_t)(bn + lrow) * K + cb;
    const __nv_bfloat16* pBl = Bl + (size_t)(bn + lrow) * K + cb;
    const uint32_t drow = (uint32_t)lrow * (SB * 2) + cb * 2;

    float acc[4][4][4];
#pragma unroll
    for (int t = 0; t < 4; t++)
#pragma unroll
        for (int u = 0; u < 4; u++)
#pragma unroll
            for (int j = 0; j < 4; j++) acc[t][u][j] = 0.f;

    const int nit = K / 32;

    auto issue = [&](int c) {
        const uint32_t ab = sbase + (uint32_t)((c & 1) * BUF_B) + drow;
        const int k0 = c * 32;
#pragma unroll
        for (int p = 0; p < 2; p++) {
            CP16(ab + p * 16,             pAh + k0 + p * 8);
            CP16(ab + ARR_B + p * 16,     pAl + k0 + p * 8);
            CP16(ab + 2 * ARR_B + p * 16, pBh + k0 + p * 8);
            CP16(ab + 3 * ARR_B + p * 16, pBl + k0 + p * 8);
        }
        CP_COMMIT();
    };

    issue(0);

    for (int c = 0; c < nit; c++) {
        if (c + 1 < nit) { issue(c + 1); CP_WAIT(1); }
        else             { CP_WAIT(0); }
        __syncthreads();

        const uint32_t ab  = sbase + (uint32_t)((c & 1) * BUF_B);
        const uint32_t uAh = ab;
        const uint32_t uAl = ab + ARR_B;
        const uint32_t uBh = ab + 2 * ARR_B;
        const uint32_t uBl = ab + 3 * ARR_B;

#pragma unroll
        for (int kk = 0; kk < 32; kk += 16) {
            uint32_t ah[4][4], al[4][4], bh[2][4], bl[2][4];
#pragma unroll
            for (int t = 0; t < 4; t++) {
                uint32_t base = (uint32_t)((wm * 64 + t * 16) * (SB * 2)) + kk * 2;
                LDX4(ah[t], uAh + base + offA);
                LDX4(al[t], uAl + base + offA);
            }
#pragma unroll
            for (int p = 0; p < 2; p++) {
                uint32_t base = (uint32_t)((wn * 32 + p * 16) * (SB * 2)) + kk * 2;
                LDX4(bh[p], uBh + base + offB);
                LDX4(bl[p], uBl + base + offB);
            }
#pragma unroll
            for (int t = 0; t < 4; t++) {
#pragma unroll
                for (int u = 0; u < 4; u++) {
                    const int p = u >> 1, o = (u & 1) * 2;
                    MMA_BF16(acc[t][u], ah[t], bh[p][o], bh[p][o + 1]);
                    MMA_BF16(acc[t][u], ah[t], bl[p][o], bl[p][o + 1]);
                    MMA_BF16(acc[t][u], al[t], bh[p][o], bh[p][o + 1]);
                }
            }
        }
        __syncthreads();
    }

    const int er = lane >> 2;
    const int ec = (lane & 3) * 2;
#pragma unroll
    for (int t = 0; t < 4; t++) {
        const int row = bm + wm * 64 + t * 16 + er;
#pragma unroll
        for (int u = 0; u < 4; u++) {
            const int col = bn + wn * 32 + u * 8 + ec;
            const float b0 = bias[col], b1 = bias[col + 1];
            float2 v0 = {acc[t][u][0] + b0, acc[t][u][1] + b1};
            float2 v1 = {acc[t][u][2] + b0, acc[t][u][3] + b1};
            *(float2*)&C[(size_t)row * N + col]       = v0;
            *(float2*)&C[(size_t)(row + 8) * N + col] = v1;
        }
    }
}

// ---------------------------------------------------------------------------
// Tensor-core flash attention (round-8 version, unchanged — best measured)
// ---------------------------------------------------------------------------
#define KSTR 72
#define ASZ  (64 * KSTR * 2)
#define BUFSZ (4 * ASZ)
#define ATTN_SMEM (2 * BUFSZ)

__global__ __launch_bounds__(128) void attn_mma(const float* __restrict__ qkv,
                                                __nv_bfloat16* __restrict__ oh,
                                                __nv_bfloat16* __restrict__ ol)
{
    extern __shared__ __align__(16) char smraw[];
    const uint32_t sb = smem_u32(smraw);

    const int tid  = threadIdx.x;
    const int w    = tid >> 5;
    const int lane = tid & 31;
    const int qt   = blockIdx.x * 64;
    const int b    = blockIdx.y / NH;
    const int h    = blockIdx.y % NH;

    const float* base = qkv + (size_t)b * SEQ * QKV_N + h * HD;

    const uint32_t offA = (uint32_t)(lane & 15) * (KSTR * 2) + ((lane & 16) ? 16 : 0);
    const uint32_t offB = (uint32_t)(((lane & 16) >> 1) + (lane & 7)) * (KSTR * 2)
                        + ((lane & 8) ? 16 : 0);

    const int lr = tid >> 1;
    const int lc = (tid & 1) * 32;
    const uint32_t stoff = (uint32_t)lr * (KSTR * 2) + lc * 2;

    {
        const float* qp = base + (size_t)(qt + lr) * QKV_N + lc;
#pragma unroll
        for (int j = 0; j < 8; j++) {
            float4 v = *(const float4*)(qp + j * 4);
            uint32_t h0, l0, h1, l1;
            split_pair(v.x * 0.125f, v.y * 0.125f, h0, l0);
            split_pair(v.z * 0.125f, v.w * 0.125f, h1, l1);
            *(uint2*)(smraw + stoff + j * 8)       = make_uint2(h0, h1);
            *(uint2*)(smraw + ASZ + stoff + j * 8) = make_uint2(l0, l1);
        }
    }
    __syncthreads();

    uint32_t qh[4][4], ql[4][4];
#pragma unroll
    for (int ks = 0; ks < 4; ks++) {
        uint32_t a = (uint32_t)(w * 16) * (KSTR * 2) + ks * 32 + offA;
        LDX4(qh[ks], sb + a);
        LDX4(ql[ks], sb + ASZ + a);
    }
    __syncthreads();

    const float* kbase = base + DIM + (size_t)lr * QKV_N + lc;
    float4 rk[8], rv[8];
#pragma unroll
    for (int j = 0; j < 8; j++) {
        rk[j] = *(const float4*)(kbase + j * 4);
        rv[j] = *(const float4*)(kbase + DIM + j * 4);
    }

    auto stage = [&](int buf) {
        char* p = smraw + buf * BUFSZ + stoff;
#pragma unroll
        for (int j = 0; j < 8; j++) {
            uint32_t h0, lo0, h1, lo1;
            split_pair(rk[j].x, rk[j].y, h0, lo0);
            split_pair(rk[j].z, rk[j].w, h1, lo1);
            *(uint2*)(p + j * 8)           = make_uint2(h0, h1);
            *(uint2*)(p + ASZ + j * 8)     = make_uint2(lo0, lo1);
            split_pair(rv[j].x, rv[j].y, h0, lo0);
            split_pair(rv[j].z, rv[j].w, h1, lo1);
            *(uint2*)(p + 2 * ASZ + j * 8) = make_uint2(h0, h1);
            *(uint2*)(p + 3 * ASZ + j * 8) = make_uint2(lo0, lo1);
        }
    };

    stage(0);
#pragma unroll
    for (int j = 0; j < 8; j++) {
        rk[j] = *(const float4*)(kbase + 64 * QKV_N + j * 4);
        rv[j] = *(const float4*)(kbase + 64 * QKV_N + DIM + j * 4);
    }
    __syncthreads();

    float oacc[8][4];
#pragma unroll
    for (int u = 0; u < 8; u++)
#pragma unroll
        for (int j = 0; j < 4; j++) oacc[u][j] = 0.f;
    float m0 = -1e30f, m1 = -1e30f, l0 = 0.f, l1 = 0.f;

    const int NT = SEQ / 64;
    for (int kt = 0; kt < NT; kt++) {
        const uint32_t bb  = sb + (uint32_t)((kt & 1) * BUFSZ);
        const uint32_t uKh = bb, uKl = bb + ASZ;
        const uint32_t uVh = bb + 2 * ASZ, uVl = bb + 3 * ASZ;

        float sacc[8][4];
#pragma unroll
        for (int u = 0; u < 8; u++)
#pragma unroll
            for (int j = 0; j < 4; j++) sacc[u][j] = 0.f;

#pragma unroll
        for (int ks = 0; ks < 4; ks++) {
#pragma unroll
            for (int np = 0; np < 4; np++) {
                uint32_t kh[4], kl[4];
                uint32_t a = (uint32_t)(np * 16) * (KSTR * 2) + ks * 32 + offB;
                LDX4(kh, uKh + a);
                LDX4(kl, uKl + a);
                const int u = np * 2;
                MMA_BF16(sacc[u],     qh[ks], kh[0], kh[1]);
                MMA_BF16(sacc[u],     qh[ks], kl[0], kl[1]);
                MMA_BF16(sacc[u],     ql[ks], kh[0], kh[1]);
                MMA_BF16(sacc[u + 1], qh[ks], kh[2], kh[3]);
                MMA_BF16(sacc[u + 1], qh[ks], kl[2], kl[3]);
                MMA_BF16(sacc[u + 1], ql[ks], kh[2], kh[3]);
            }
        }

        float mt0 = -1e30f, mt1 = -1e30f;
#pragma unroll
        for (int u = 0; u < 8; u++) {
            mt0 = fmaxf(mt0, fmaxf(sacc[u][0], sacc[u][1]));
            mt1 = fmaxf(mt1, fmaxf(sacc[u][2], sacc[u][3]));
        }
        mt0 = fmaxf(mt0, __shfl_xor_sync(0xffffffffu, mt0, 1));
        mt0 = fmaxf(mt0, __shfl_xor_sync(0xffffffffu, mt0, 2));
        mt1 = fmaxf(mt1, __shfl_xor_sync(0xffffffffu, mt1, 1));
        mt1 = fmaxf(mt1, __shfl_xor_sync(0xffffffffu, mt1, 2));

        const float mn0 = fmaxf(m0, mt0);
        const float mn1 = fmaxf(m1, mt1);
        const float a0 = __expf(m0 - mn0);
        const float a1 = __expf(m1 - mn1);

        float ls0 = 0.f, ls1 = 0.f;
#pragma unroll
        for (int u = 0; u < 8; u++) {
            sacc[u][0] = __expf(sacc[u][0] - mn0);
            sacc[u][1] = __expf(sacc[u][1] - mn0);
            sacc[u][2] = __expf(sacc[u][2] - mn1);
            sacc[u][3] = __expf(sacc[u][3] - mn1);
            ls0 += sacc[u][0] + sacc[u][1];
            ls1 += sacc[u][2] + sacc[u][3];
        }
        ls0 += __shfl_xor_sync(0xffffffffu, ls0, 1);
        ls0 += __shfl_xor_sync(0xffffffffu, ls0, 2);
        ls1 += __shfl_xor_sync(0xffffffffu, ls1, 1);
        ls1 += __shfl_xor_sync(0xffffffffu, ls1, 2);
        l0 = l0 * a0 + ls0;  m0 = mn0;
        l1 = l1 * a1 + ls1;  m1 = mn1;

#pragma unroll
        for (int u = 0; u < 8; u++) {
            oacc[u][0] *= a0; oacc[u][1] *= a0;
            oacc[u][2] *= a1; oacc[u][3] *= a1;
        }

        if (kt + 1 < NT) {
            stage((kt + 1) & 1);
            if (kt + 2 < NT) {
                const float* np = kbase + (size_t)(kt + 2) * 64 * QKV_N;
#pragma unroll
                for (int j = 0; j < 8; j++) {
                    rk[j] = *(const float4*)(np + j * 4);
                    rv[j] = *(const float4*)(np + DIM + j * 4);
                }
            }
        }

        uint32_t pah[4][4], pal[4][4];
#pragma unroll
        for (int t = 0; t < 4; t++) {
            split_pair(sacc[2 * t][0],     sacc[2 * t][1],     pah[t][0], pal[t][0]);
            split_pair(sacc[2 * t][2],     sacc[2 * t][3],     pah[t][1], pal[t][1]);
            split_pair(sacc[2 * t + 1][0], sacc[2 * t + 1][1], pah[t][2], pal[t][2]);
            split_pair(sacc[2 * t + 1][2], sacc[2 * t + 1][3], pah[t][3], pal[t][3]);
        }

#pragma unroll
        for (int t = 0; t < 4; t++) {
#pragma unroll
            for (int nd = 0; nd < 4; nd++) {
                uint32_t vh[4], vl[4];
                uint32_t a = (uint32_t)(t * 16) * (KSTR * 2) + nd * 32 + offB;
                LDX4T(vh, uVh + a);
                LDX4T(vl, uVl + a);
                const int u = nd * 2;
                MMA_BF16(oacc[u],     pah[t], vh[0], vh[2]);
                MMA_BF16(oacc[u],     pah[t], vl[0], vl[2]);
                MMA_BF16(oacc[u],     pal[t], vh[0], vh[2]);
                MMA_BF16(oacc[u + 1], pah[t], vh[1], vh[3]);
                MMA_BF16(oacc[u + 1], pah[t], vl[1], vl[3]);
                MMA_BF16(oacc[u + 1], pal[t], vh[1], vh[3]);
            }
        }
        __syncthreads();
    }

    const float inv0 = 1.f / l0;
    const float inv1 = 1.f / l1;
    const int er = lane >> 2;
    const int ec = (lane & 3) * 2;
    const size_t tok0 = (size_t)b * SEQ + qt + w * 16 + er;
    const int colb = h * HD + ec;
#pragma unroll
    for (int u = 0; u < 8; u++) {
        const int col = colb + u * 8;
        uint32_t hp, lp;
        split_pair(oacc[u][0] * inv0, oacc[u][1] * inv0, hp, lp);
        *(uint32_t*)(oh + tok0 * DIM + col) = hp;
        *(uint32_t*)(ol + tok0 * DIM + col) = lp;
        split_pair(oacc[u][2] * inv1, oacc[u][3] * inv1, hp, lp);
        *(uint32_t*)(oh + (tok0 + 8) * DIM + col) = hp;
        *(uint32_t*)(ol + (tok0 + 8) * DIM + col) = lp;
    }
}

extern "C" void kernel_launch(void* const* d_in, const int* in_sizes, int n_in,
                              void* d_out, int out_size)
{
    const float* x      = (const float*)d_in[0];
    const float* qkv_w  = (const float*)d_in[1];
    const float* qkv_b  = (const float*)d_in[2];
    const float* proj_w = (const float*)d_in[3];
    const float* proj_b = (const float*)d_in[4];
    float* out = (float*)d_out;

    float* qkv;
    __nv_bfloat16 *xh, *xl, *qwh, *qwl, *pwh, *pwl, *ah, *al;
    cudaGetSymbolAddress((void**)&qkv, g_qkv);
    cudaGetSymbolAddress((void**)&xh,  g_xh);
    cudaGetSymbolAddress((void**)&xl,  g_xl);
    cudaGetSymbolAddress((void**)&qwh, g_qwh);
    cudaGetSymbolAddress((void**)&qwl, g_qwl);
    cudaGetSymbolAddress((void**)&pwh, g_pwh);
    cudaGetSymbolAddress((void**)&pwl, g_pwl);
    cudaGetSymbolAddress((void**)&ah,  g_ah);
    cudaGetSymbolAddress((void**)&al,  g_al);

    cudaFuncSetAttribute(gemm_bf16x3,
                         cudaFuncAttributeMaxDynamicSharedMemorySize, GEMM_SMEM);
    cudaFuncSetAttribute(attn_mma,
                         cudaFuncAttributeMaxDynamicSharedMemorySize, ATTN_SMEM);

    // splits
    const int nx = M_TOT * DIM, nqw = QKV_N * DIM, npw = DIM * DIM;
    split_kernel<<<(nx / 4 + 255) / 256, 256>>>(x, xh, xl, nx);
    split_kernel<<<(nqw / 4 + 255) / 256, 256>>>(qkv_w, qwh, qwl, nqw);
    split_kernel<<<(npw / 4 + 255) / 256, 256>>>(proj_w, pwh, pwl, npw);

    // QKV projection: [8192, 2304]
    gemm_bf16x3<<<dim3(QKV_N / 128, M_TOT / 128), 256, GEMM_SMEM>>>(
        xh, xl, qwh, qwl, qkv_b, qkv, QKV_N, DIM);

    // Attention (tensor-core, pipelined) -> bf16 hi/lo
    attn_mma<<<dim3(SEQ / 64, BATCH * NH), 128, ATTN_SMEM>>>(qkv, ah, al);

    // Output projection: [8192, 768]
    gemm_bf16x3<<<dim3(DIM / 128, M_TOT / 128), 256, GEMM_SMEM>>>(
        ah, al, pwh, pwl, proj_b, out, DIM, DIM);
}